// round 12
// baseline (speedup 1.0000x reference)
#include <cuda_runtime.h>
#include <cstdint>

// PowerSpectrum: values[S,N,L,M,Q] f32 -> out[S,N,L*Q*Q] f32
// out[s,n,l,q,p] = rsqrt(2l+1) * sum_{m<2l+1} v[m,q]*v[m,p]
// Shapes: S=4, N=2000, L=4, M=7, Q=64 -> 32000 (s,n,l) tiles.
//
// R12 experiment: persistent CTAs with BLOCKED tile assignment. 1184
// CTAs (148 SMs x 8), each owns a contiguous run of ~27 tiles = ~432KB
// of sequential output writes, instead of 32000 interleaved 16KB
// streams. Tests whether DRAM write-stream contiguity lifts the ~6.0
// TB/s plateau or whether the 2KB-grain LTS hash makes it irrelevant.
// Compute core is the proven R4 8x4 register tile.

#define L_DIM 4
#define M_DIM 7
#define Q_DIM 64
#define TILE_IN   (M_DIM * Q_DIM)   // 448 floats
#define TILE_OUT  (Q_DIM * Q_DIM)   // 4096 floats
#define NUM_CTAS  1184              // 148 SMs * 8 resident CTAs

template<int MM>
__device__ __forceinline__ void gram_tile(const float (*__restrict__ sv)[Q_DIM],
                                          float* __restrict__ ot, int tid)
{
    const int p0 = (tid & 15) << 2;  // 0,4,...,60
    const int q0 = (tid >> 4) << 3;  // 0,8,...,56

    const float cg = rsqrtf((float)MM);

    float4 acc[8];
    #pragma unroll
    for (int r = 0; r < 8; r++) acc[r] = make_float4(0.f, 0.f, 0.f, 0.f);

    #pragma unroll
    for (int m = 0; m < MM; m++) {
        const float4 b  = *(const float4*)&sv[m][p0];
        const float4 a0 = *(const float4*)&sv[m][q0];
        const float4 a1 = *(const float4*)&sv[m][q0 + 4];
        const float ar[8] = {a0.x, a0.y, a0.z, a0.w, a1.x, a1.y, a1.z, a1.w};
        #pragma unroll
        for (int r = 0; r < 8; r++) {
            acc[r].x += ar[r] * b.x;
            acc[r].y += ar[r] * b.y;
            acc[r].z += ar[r] * b.z;
            acc[r].w += ar[r] * b.w;
        }
    }

    #pragma unroll
    for (int r = 0; r < 8; r++) {
        float4 o = make_float4(acc[r].x * cg, acc[r].y * cg,
                               acc[r].z * cg, acc[r].w * cg);
        __stcs((float4*)(ot + (size_t)(q0 + r) * Q_DIM + p0), o);
    }
}

__global__ __launch_bounds__(128)
void powerspectrum_kernel(const float* __restrict__ values,
                          float* __restrict__ out, int tiles)
{
    __shared__ float sv[M_DIM][Q_DIM];     // 1792 B

    const int tid = threadIdx.x;

    // Blocked assignment: CTA b owns tiles [b*chunk, min((b+1)*chunk, tiles))
    const int chunk = (tiles + NUM_CTAS - 1) / NUM_CTAS;
    const int t0    = blockIdx.x * chunk;
    const int t1    = min(t0 + chunk, tiles);

    for (int tile = t0; tile < t1; tile++) {
        const float* vt = values + (size_t)tile * TILE_IN;
        float*       ot = out    + (size_t)tile * TILE_OUT;
        const int l = tile & (L_DIM - 1);

        if (tid < TILE_IN / 4)
            ((float4*)&sv[0][0])[tid] = ((const float4*)vt)[tid];
        __syncthreads();

        switch (l) {
            case 0: gram_tile<1>(sv, ot, tid); break;
            case 1: gram_tile<3>(sv, ot, tid); break;
            case 2: gram_tile<5>(sv, ot, tid); break;
            default: gram_tile<7>(sv, ot, tid); break;
        }
        __syncthreads();   // sv reused next iteration
    }
}

extern "C" void kernel_launch(void* const* d_in, const int* in_sizes, int n_in,
                              void* d_out, int out_size)
{
    const float* values = (const float*)d_in[0];
    float* out = (float*)d_out;

    const int tiles = in_sizes[0] / TILE_IN;   // S*N*L = 32000

    powerspectrum_kernel<<<NUM_CTAS, 128>>>(values, out, tiles);
}

// round 13
// speedup vs baseline: 1.4139x; 1.4139x over previous
#include <cuda_runtime.h>
#include <cstdint>

// PowerSpectrum: values[S,N,L,M,Q] f32 -> out[S,N,L*Q*Q] f32
// out[s,n,l,q,p] = rsqrt(2l+1) * sum_{m<2l+1} v[m,q]*v[m,p]
// Shapes: S=4, N=2000, L=4, M=7, Q=64 -> 32000 (s,n,l) tiles.
//
// SESSION FINAL (R4 design; 88.5us bench / 85.6us ncu best, DRAM ~76%,
// HBM ~6.1TB/s). Write-BW bound: 524MB compulsory f32 output drains as
// a pure write stream at the device's path-independent ceiling.
// Falsified alternatives: CTA merging (R5), 8x8 tile (R6, reg pressure),
// occupancy cap (R8), TMA bulk store (R9), persistent blocked CTAs
// (R12, lost load/store overlap). One-CTA-per-tile wins because CTA
// turnover naturally overlaps new-tile loads with old-tile store drain.
//
// Design: one CTA per (s,n,l) tile. 1.8KB input to SMEM, 8x4 per-thread
// register block (1.5 B LDS per FFMA), compile-time m-count per l
// (1/3/5/7 -- invalid m rows never touched), streaming STG.128 stores
// (.cs keeps the write-once output from evicting the L2-resident input),
// fully coalesced 256B row segments.

#define L_DIM 4
#define M_DIM 7
#define Q_DIM 64
#define TILE_IN   (M_DIM * Q_DIM)   // 448 floats
#define TILE_OUT  (Q_DIM * Q_DIM)   // 4096 floats

template<int MM>
__device__ __forceinline__ void gram_tile(const float (*__restrict__ sv)[Q_DIM],
                                          float* __restrict__ ot, int tid)
{
    const int p0 = (tid & 15) << 2;  // 0,4,...,60
    const int q0 = (tid >> 4) << 3;  // 0,8,...,56

    const float cg = rsqrtf((float)MM);

    float4 acc[8];
    #pragma unroll
    for (int r = 0; r < 8; r++) acc[r] = make_float4(0.f, 0.f, 0.f, 0.f);

    #pragma unroll
    for (int m = 0; m < MM; m++) {
        const float4 b  = *(const float4*)&sv[m][p0];
        const float4 a0 = *(const float4*)&sv[m][q0];
        const float4 a1 = *(const float4*)&sv[m][q0 + 4];
        const float ar[8] = {a0.x, a0.y, a0.z, a0.w, a1.x, a1.y, a1.z, a1.w};
        #pragma unroll
        for (int r = 0; r < 8; r++) {
            acc[r].x += ar[r] * b.x;
            acc[r].y += ar[r] * b.y;
            acc[r].z += ar[r] * b.z;
            acc[r].w += ar[r] * b.w;
        }
    }

    // Streaming stores: 16 threads (same q-group) cover one full 256B
    // output row; fully coalesced. 8 independent STG.128 per thread.
    #pragma unroll
    for (int r = 0; r < 8; r++) {
        float4 o = make_float4(acc[r].x * cg, acc[r].y * cg,
                               acc[r].z * cg, acc[r].w * cg);
        __stcs((float4*)(ot + (size_t)(q0 + r) * Q_DIM + p0), o);
    }
}

__global__ __launch_bounds__(128)
void powerspectrum_kernel(const float* __restrict__ values,
                          float* __restrict__ out)
{
    const int tile = blockIdx.x;           // tile = (s*N + n)*L + l
    const int l    = tile & (L_DIM - 1);

    const float* vt = values + (size_t)tile * TILE_IN;
    float*       ot = out    + (size_t)tile * TILE_OUT;

    __shared__ float sv[M_DIM][Q_DIM];     // 1792 B

    const int tid = threadIdx.x;

    // 448 floats = 112 float4 loads; threads 0..111
    if (tid < TILE_IN / 4)
        ((float4*)&sv[0][0])[tid] = ((const float4*)vt)[tid];
    __syncthreads();

    switch (l) {
        case 0: gram_tile<1>(sv, ot, tid); break;
        case 1: gram_tile<3>(sv, ot, tid); break;
        case 2: gram_tile<5>(sv, ot, tid); break;
        default: gram_tile<7>(sv, ot, tid); break;
    }
}

extern "C" void kernel_launch(void* const* d_in, const int* in_sizes, int n_in,
                              void* d_out, int out_size)
{
    const float* values = (const float*)d_in[0];
    float* out = (float*)d_out;

    const int tiles = in_sizes[0] / TILE_IN;   // S*N*L = 32000

    powerspectrum_kernel<<<tiles, 128>>>(values, out);
}